// round 2
// baseline (speedup 1.0000x reference)
#include <cuda_runtime.h>
#include <math.h>

#define NB    128
#define ND    32
#define NN0   128
#define NN1   128
#define NPAIR (NN0 * NN1)
#define EPS2  0.25f
#define EPS4  0.0625f
#define WPC   8          // warps per CTA in main kernel
#define GX    74         // pair-chunk CTAs (x), 4 batch groups (y) -> 296 CTAs = 2/SM

// ---------------- device scratch (static: no allocation allowed) -------------
// Coefficient planes, all indexed [pair][dim]:
//   g_ab: {a = -0.5/Sigma, b = Mut/Sigma}
//   g_ka: {K = St/Sigma,   A = v - K*Mut}
__device__ float2 g_ab[NPAIR * ND];
__device__ float2 g_ka[NPAIR * ND];
__device__ float  g_c [NPAIR];          // per-pair constant: sum_n a*Mut^2 - 0.5*log(Sigma)
// Accumulators (zeroed each launch)
__device__ float  g_sk [NB * ND];       // sum_p W * K
__device__ float  g_sa [NB * ND];       // sum_p W * A
__device__ float  g_den[NB];            // sum_p W

// ---------------- kernel 0: zero accumulators --------------------------------
__global__ void kzero() {
    int i = blockIdx.x * blockDim.x + threadIdx.x;
    if (i < NB * ND) { g_sk[i] = 0.f; g_sa[i] = 0.f; }
    if (i < NB)      { g_den[i] = 0.f; }
}

// ---------------- kernel 1: precompute coefficient planes --------------------
// One warp per pair, lane = dim.
__global__ void kprep(const float* __restrict__ tptr,
                      const float* __restrict__ Mu0,
                      const float* __restrict__ Mu1,
                      const float* __restrict__ S0,
                      const float* __restrict__ S1) {
    int p = blockIdx.x * (blockDim.x >> 5) + (threadIdx.x >> 5);
    int n = threadIdx.x & 31;
    if (p >= NPAIR) return;
    int i = p >> 7;       // N0 index
    int j = p & 127;      // N1 index

    float t = tptr[0];
    float u = 1.f - t;

    float s0 = S0[i * ND + n];
    float s1 = S1[j * ND + n];
    float Ds = sqrtf(4.f * s0 * s1 + EPS4);
    float Cs = 0.5f * (Ds - EPS2);
    float Sigma = u * u * s0 + t * t * s1 + 2.f * t * u * Cs + EPS2 * t * u;
    float St = (t * s1 + u * Cs) - (u * s0 + t * Cs) - EPS2 * t;

    float inv = 1.0f / Sigma;
    float K   = St * inv;

    float m0  = Mu0[i * ND + n];
    float m1  = Mu1[j * ND + n];
    float Mut = u * m0 + t * m1;
    float v   = m1 - m0;

    float a  = -0.5f * inv;
    float bq = Mut * inv;           // = -2*a*Mut
    float A  = v - K * Mut;

    float cterm = a * Mut * Mut - 0.5f * logf(Sigma);

    g_ab[p * ND + n] = make_float2(a, bq);
    g_ka[p * ND + n] = make_float2(K, A);

    // warp-reduce cterm over dims
    #pragma unroll
    for (int o = 16; o; o >>= 1)
        cterm += __shfl_xor_sync(0xffffffffu, cterm, o);
    if (n == 0) g_c[p] = cterm;
}

// ---------------- kernel 2: main accumulation --------------------------------
// lane = batch within a 32-batch group (blockIdx.y selects the group).
// Each warp walks pairs [pbeg+w :: WPC :: pend), coefficients are lane-uniform
// broadcast loads from L2-resident planes. Per pair: 128 FFMA + 1 exp.
__global__ void __launch_bounds__(32 * WPC, 2)
kmain(const float* __restrict__ X, const float* __restrict__ Lam) {
    __shared__ float red[32 * 65];   // [lane(batch)][ sk(32) | sa(32) | den ]

    int lane = threadIdx.x & 31;
    int w    = threadIdx.x >> 5;
    int b    = blockIdx.y * 32 + lane;

    // batch-private state in registers
    float x[ND];
    #pragma unroll
    for (int n = 0; n < ND; n++) x[n] = X[b * ND + n];
    float sk[ND], sa[ND];
    #pragma unroll
    for (int n = 0; n < ND; n++) { sk[n] = 0.f; sa[n] = 0.f; }
    float den = 0.f;

    // zero the shared reduction buffer
    for (int e = threadIdx.x; e < 32 * 65; e += 32 * WPC) red[e] = 0.f;
    __syncthreads();

    const int per  = (NPAIR + gridDim.x - 1) / gridDim.x;
    const int pbeg = blockIdx.x * per;
    const int pend = min(pbeg + per, NPAIR);

    for (int p = pbeg + w; p < pend; p += WPC) {
        const float4* ab4 = reinterpret_cast<const float4*>(g_ab + p * ND);
        const float4* ka4 = reinterpret_cast<const float4*>(g_ka + p * ND);

        float lw = g_c[p];
        #pragma unroll
        for (int k = 0; k < ND / 2; k++) {
            float4 q = ab4[k];                       // dims 2k, 2k+1: {a0,b0,a1,b1}
            lw = fmaf(x[2 * k],     fmaf(q.x, x[2 * k],     q.y), lw);
            lw = fmaf(x[2 * k + 1], fmaf(q.z, x[2 * k + 1], q.w), lw);
        }
        lw = fminf(fmaxf(lw, -50.f), 50.f);
        float wt = __expf(lw) * __ldg(Lam + p);

        den += wt;
        #pragma unroll
        for (int k = 0; k < ND / 2; k++) {
            float4 r = ka4[k];                       // {K0,A0,K1,A1}
            sk[2 * k]     = fmaf(wt, r.x, sk[2 * k]);
            sa[2 * k]     = fmaf(wt, r.y, sa[2 * k]);
            sk[2 * k + 1] = fmaf(wt, r.z, sk[2 * k + 1]);
            sa[2 * k + 1] = fmaf(wt, r.w, sa[2 * k + 1]);
        }
    }

    // combine the 8 warps through shared atomics (lanes hit distinct banks)
    float* base = red + lane * 65;
    #pragma unroll
    for (int n = 0; n < ND; n++) {
        atomicAdd(base + n,      sk[n]);
        atomicAdd(base + 32 + n, sa[n]);
    }
    atomicAdd(base + 64, den);
    __syncthreads();

    // one CTA-level partial -> global RED
    for (int e = threadIdx.x; e < 32 * 65; e += 32 * WPC) {
        float vsum = red[e];
        int l   = e / 65;
        int idx = e - l * 65;
        int bb  = blockIdx.y * 32 + l;
        if (idx < 32)      atomicAdd(&g_sk[bb * ND + idx], vsum);
        else if (idx < 64) atomicAdd(&g_sa[bb * ND + idx - 32], vsum);
        else               atomicAdd(&g_den[bb], vsum);
    }
}

// ---------------- kernel 3: finalize -----------------------------------------
__global__ void kfinal(const float* __restrict__ X, float* __restrict__ out) {
    int i = blockIdx.x * blockDim.x + threadIdx.x;
    if (i >= NB * ND) return;
    int b = i / ND;
    out[i] = (X[i] * g_sk[i] + g_sa[i]) / g_den[b];
}

// ---------------- launch ------------------------------------------------------
extern "C" void kernel_launch(void* const* d_in, const int* in_sizes, int n_in,
                              void* d_out, int out_size) {
    const float* X   = (const float*)d_in[0];
    const float* t   = (const float*)d_in[1];
    const float* Mu0 = (const float*)d_in[2];
    const float* Mu1 = (const float*)d_in[3];
    const float* S0  = (const float*)d_in[4];
    const float* S1  = (const float*)d_in[5];
    const float* Lam = (const float*)d_in[6];
    float* out = (float*)d_out;

    kzero<<<(NB * ND + 255) / 256, 256>>>();
    kprep<<<NPAIR / 8, 256>>>(t, Mu0, Mu1, S0, S1);   // 8 warps/CTA, 1 pair/warp
    dim3 grid(GX, 4);
    kmain<<<grid, 32 * WPC>>>(X, Lam);
    kfinal<<<(NB * ND + 255) / 256, 256>>>(X, out);
}

// round 6
// speedup vs baseline: 1.7580x; 1.7580x over previous
#include <cuda_runtime.h>
#include <math.h>
#include <stdint.h>

#define NB    128
#define ND    32
#define NPAIR 16384
#define EPS2  0.25f
#define EPS4  0.0625f
#define GX    74                 // pair-chunk CTAs
#define PER   222                // ceil(NPAIR/GX)
#define TILE  32                 // pairs per staged tile
#define RECF4 33                 // float4s per pair record (16 ab + 16 ka + {c,lam})
#define RECB  (RECF4*16)         // 528 bytes
#define TILEB (TILE*RECB)        // 16896 bytes per stage

typedef unsigned long long u64;

// ---------------- packed f32x2 helpers ---------------------------------------
__device__ __forceinline__ u64 pack2(float lo, float hi) {
    u64 r; asm("mov.b64 %0,{%1,%2};" : "=l"(r) : "f"(lo), "f"(hi)); return r;
}
__device__ __forceinline__ void unpack2(u64 v, float& lo, float& hi) {
    asm("mov.b64 {%0,%1},%2;" : "=f"(lo), "=f"(hi) : "l"(v));
}
__device__ __forceinline__ u64 fma2(u64 a, u64 b, u64 c) {
    u64 d; asm("fma.rn.f32x2 %0,%1,%2,%3;" : "=l"(d) : "l"(a), "l"(b), "l"(c)); return d;
}
__device__ __forceinline__ void lds_v2u64(uint32_t addr, u64& a, u64& b) {
    asm volatile("ld.shared.v2.u64 {%0,%1},[%2];" : "=l"(a), "=l"(b) : "r"(addr));
}
__device__ __forceinline__ uint32_t smem_u32(const void* p) {
    uint32_t a;
    asm("{ .reg .u64 t; cvta.to.shared.u64 t, %1; cvt.u32.u64 %0, t; }" : "=r"(a) : "l"(p));
    return a;
}
// LDGSTS 16B + group ops
__device__ __forceinline__ void cp16(uint32_t dst, const void* src) {
    asm volatile("cp.async.cg.shared.global [%0],[%1],16;" :: "r"(dst), "l"(src) : "memory");
}
__device__ __forceinline__ void cp_commit() {
    asm volatile("cp.async.commit_group;" ::: "memory");
}
template <int N>
__device__ __forceinline__ void cp_wait() {
    asm volatile("cp.async.wait_group %0;" :: "n"(N) : "memory");
}

// ---------------- device scratch ---------------------------------------------
// Record per pair: f4[0..15]  = {a2k, a2k+1, b2k, b2k+1}
//                  f4[16..31] = {K2k, K2k+1, A2k, A2k+1}
//                  f4[32]     = {c, lam, 0, 0}
__device__ float4 g_rec[NPAIR * RECF4];
// per-CTA partials: [gy*GX+gx][batchLane(32)][sk32|sa32|den]
__device__ float  g_part[4 * GX * 32 * 65];

// ---------------- kernel 1: precompute records --------------------------------
__global__ void kprep(const float* __restrict__ tptr,
                      const float* __restrict__ Mu0,
                      const float* __restrict__ Mu1,
                      const float* __restrict__ S0,
                      const float* __restrict__ S1,
                      const float* __restrict__ Lam) {
    int p = blockIdx.x * (blockDim.x >> 5) + (threadIdx.x >> 5);
    int n = threadIdx.x & 31;
    if (p >= NPAIR) return;
    int i = p >> 7, j = p & 127;

    float t = tptr[0];
    float u = 1.f - t;

    float s0 = S0[i * ND + n];
    float s1 = S1[j * ND + n];
    float Ds = sqrtf(fmaf(4.f * s0, s1, EPS4));
    float Cs = 0.5f * (Ds - EPS2);
    float Sigma = u * u * s0 + t * t * s1 + 2.f * t * u * Cs + EPS2 * t * u;
    float St = (t * s1 + u * Cs) - (u * s0 + t * Cs) - EPS2 * t;

    float inv = __fdividef(1.0f, Sigma);
    float K   = St * inv;

    float m0  = Mu0[i * ND + n];
    float m1  = Mu1[j * ND + n];
    float Mut = fmaf(t, m1, u * m0);
    float v   = m1 - m0;

    float a  = -0.5f * inv;
    float bq = Mut * inv;
    float A  = fmaf(-K, Mut, v);

    float cterm = fmaf(a * Mut, Mut, -0.5f * __logf(Sigma));
    #pragma unroll
    for (int o = 16; o; o >>= 1)
        cterm += __shfl_xor_sync(0xffffffffu, cterm, o);

    // shuffle-assemble float4s: even lanes own ab slot k=n/2, odd lanes own ka slot
    float aP = __shfl_xor_sync(0xffffffffu, a, 1);
    float bP = __shfl_xor_sync(0xffffffffu, bq, 1);
    float KP = __shfl_xor_sync(0xffffffffu, K, 1);
    float AP = __shfl_xor_sync(0xffffffffu, A, 1);

    float4* r4 = g_rec + p * RECF4;
    int k = n >> 1;
    if ((n & 1) == 0) r4[k]      = make_float4(a, aP, bq, bP);
    else              r4[16 + k] = make_float4(KP, K, AP, A);
    if (n == 0)       r4[32]     = make_float4(cterm, __ldg(Lam + p), 0.f, 0.f);
}

// ---------------- kernel 2: main accumulation ---------------------------------
// lane = batch (blockIdx.y selects the 32-batch group). Coefficients staged
// through a cp.async double buffer; hot loop is pure LDS + packed f32x2 FMA.
__global__ void __launch_bounds__(256, 2)
kmain(const float* __restrict__ X) {
    __shared__ __align__(16) float4 sbuf[2][TILE * RECF4];   // 2 x 16896 B

    const int tid  = threadIdx.x;
    const int lane = tid & 31;
    const int w    = tid >> 5;
    const int b    = blockIdx.y * 32 + lane;

    const uint32_t sb0 = smem_u32(&sbuf[0][0]);

    // per-batch X, packed
    u64 xp[16];
    {
        const float4* X4 = reinterpret_cast<const float4*>(X + b * ND);
        #pragma unroll
        for (int q = 0; q < 8; q++) {
            float4 xv = X4[q];
            xp[2 * q]     = pack2(xv.x, xv.y);
            xp[2 * q + 1] = pack2(xv.z, xv.w);
        }
    }
    u64 skp[16], sap[16];
    const u64 zz = pack2(0.f, 0.f);
    #pragma unroll
    for (int k = 0; k < 16; k++) { skp[k] = zz; sap[k] = zz; }
    float den = 0.f;

    const int pbeg  = blockIdx.x * PER;
    const int cnt   = min(PER, NPAIR - pbeg);
    const int ntile = (cnt + TILE - 1) / TILE;

    // prologue: stage tile 0
    {
        int nw = min(TILE, cnt) * RECF4;                 // 16B words
        const float4* src = g_rec + pbeg * RECF4;
        for (int wrd = tid; wrd < nw; wrd += 256)
            cp16(sb0 + wrd * 16, src + wrd);
        cp_commit();
    }

    for (int tI = 0; tI < ntile; tI++) {
        const int s = tI & 1;

        // stage tile tI+1 into the other buffer (safe: last read at tile tI-1,
        // protected by the end-of-iteration __syncthreads)
        if (tI + 1 < ntile) {
            int nw = min(TILE, cnt - (tI + 1) * TILE) * RECF4;
            const float4* src = g_rec + (pbeg + (tI + 1) * TILE) * RECF4;
            uint32_t dst = sb0 + (s ^ 1) * TILEB;
            for (int wrd = tid; wrd < nw; wrd += 256)
                cp16(dst + wrd * 16, src + wrd);
            cp_commit();
            cp_wait<1>();          // tile tI's group complete
        } else {
            cp_wait<0>();
        }
        __syncthreads();

        const int tc = min(TILE, cnt - tI * TILE);
        for (int j = w; j < tc; j += 8) {
            uint32_t rec = sb0 + s * TILEB + j * RECB;

            // logw = c + sum a*x^2 + b*x   (packed, 2 chains)
            u64 lw0 = zz, lw1 = zz;
            #pragma unroll
            for (int k = 0; k < 16; k += 2) {
                u64 ap, bp;
                lds_v2u64(rec + k * 16, ap, bp);
                lw0 = fma2(xp[k], fma2(ap, xp[k], bp), lw0);
                u64 ap1, bp1;
                lds_v2u64(rec + (k + 1) * 16, ap1, bp1);
                lw1 = fma2(xp[k + 1], fma2(ap1, xp[k + 1], bp1), lw1);
            }
            float cl0, cl1;
            asm volatile("ld.shared.v2.f32 {%0,%1},[%2];"
                         : "=f"(cl0), "=f"(cl1) : "r"(rec + 512));
            float a0, a1, b0v, b1v;
            unpack2(lw0, a0, a1);
            unpack2(lw1, b0v, b1v);
            float lw = (a0 + a1) + (b0v + b1v) + cl0;
            lw = fminf(fmaxf(lw, -50.f), 50.f);
            float wt = __expf(lw) * cl1;
            den += wt;
            u64 wtp = pack2(wt, wt);

            #pragma unroll
            for (int k = 0; k < 16; k++) {
                u64 kp, Ap;
                lds_v2u64(rec + 256 + k * 16, kp, Ap);
                skp[k] = fma2(wtp, kp, skp[k]);
                sap[k] = fma2(wtp, Ap, sap[k]);
            }
        }
        __syncthreads();           // protect stage s from next overwrite
    }

    // -------- CTA reduction (reuse sbuf as red[32][65]) --------
    float* red = reinterpret_cast<float*>(&sbuf[0][0]);
    for (int e = tid; e < 32 * 65; e += 256) red[e] = 0.f;
    __syncthreads();

    float* base = red + lane * 65;
    #pragma unroll
    for (int k = 0; k < 16; k++) {
        float s0v, s1v;
        unpack2(skp[k], s0v, s1v);
        atomicAdd(base + 2 * k,     s0v);
        atomicAdd(base + 2 * k + 1, s1v);
        unpack2(sap[k], s0v, s1v);
        atomicAdd(base + 32 + 2 * k,     s0v);
        atomicAdd(base + 32 + 2 * k + 1, s1v);
    }
    atomicAdd(base + 64, den);
    __syncthreads();

    float* dst = g_part + (blockIdx.y * GX + blockIdx.x) * (32 * 65);
    for (int e = tid; e < 32 * 65; e += 256) dst[e] = red[e];
}

// ---------------- kernel 3: reduce partials + finalize -------------------------
__global__ void kfinal(const float* __restrict__ X, float* __restrict__ out) {
    __shared__ float sm[65];
    int bb = blockIdx.x;           // batch
    int i  = threadIdx.x;
    int gy = bb >> 5, ln = bb & 31;
    if (i < 65) {
        const float* p = g_part + (gy * GX) * (32 * 65) + ln * 65 + i;
        float s = 0.f;
        #pragma unroll 2
        for (int gx = 0; gx < GX; gx++) s += p[gx * (32 * 65)];
        sm[i] = s;
    }
    __syncthreads();
    if (i < ND) {
        float num = fmaf(X[bb * ND + i], sm[i], sm[32 + i]);
        out[bb * ND + i] = num / sm[64];
    }
}

// ---------------- launch ------------------------------------------------------
extern "C" void kernel_launch(void* const* d_in, const int* in_sizes, int n_in,
                              void* d_out, int out_size) {
    const float* X   = (const float*)d_in[0];
    const float* t   = (const float*)d_in[1];
    const float* Mu0 = (const float*)d_in[2];
    const float* Mu1 = (const float*)d_in[3];
    const float* S0  = (const float*)d_in[4];
    const float* S1  = (const float*)d_in[5];
    const float* Lam = (const float*)d_in[6];
    float* out = (float*)d_out;

    kprep<<<NPAIR / 16, 512>>>(t, Mu0, Mu1, S0, S1, Lam);   // 16 warps/CTA
    dim3 grid(GX, 4);
    kmain<<<grid, 256>>>(X);
    kfinal<<<NB, 96>>>(X, out);
}